// round 15
// baseline (speedup 1.0000x reference)
#include <cuda_runtime.h>
#include <math.h>

#define CC 512
#define LV 196
#define BV 64
#define BT 32
#define NW 24
#define NK 98
#define KP 49
#define HH 102
#define OFFMASK (BV*BT)

typedef unsigned long long ull;

#define FMA2(d, a, b) asm("fma.rn.f32x2 %0, %1, %2, %0;" : "+l"(d) : "l"(a), "l"(b))
__device__ __forceinline__ ull dup2(float w) {
    ull r;
    asm("mov.b64 %0, {%1, %1};" : "=l"(r) : "r"(__float_as_uint(w)));
    return r;
}
__device__ __forceinline__ float sum2(ull a) {
    unsigned lo, hi;
    asm("mov.b64 {%0, %1}, %2;" : "=r"(lo), "=r"(hi) : "l"(a));
    return __uint_as_float(lo) + __uint_as_float(hi);
}

// ---------------- device scratch (no allocation allowed) ----------------
__device__ float d_mu[BV*LV];
__device__ float d_rs[BV*LV];
__device__ float d_invn_img[BV*LV];
__device__ float d_imgglo[BV*CC];
__device__ float d_capglo[BT*CC];
__device__ float d_capinv[BT*NW];
__device__ float d_score[BT*BV*LV];
__device__ int   d_kidx[BT*BV*NK];
__device__ float d_wnon[BT*BV*LV];
__device__ float d_extra[BT*BV*CC];
__device__ float d_G1[CC*HH];
__device__ float d_cs[HH];
__device__ float d_bb[HH];
__device__ float d_L[BV*LV*KP];   // precomputed (scaled) logits per (v,l,p)

// ---------------- row stats for img: mean, rsigma(LN), inv l2 norm ------
__global__ void kRowStats(const float* __restrict__ img) {
    int row = blockIdx.x;  // v*LV + l
    const float* p = img + (size_t)row * CC;
    float s = 0.f, ss = 0.f;
    for (int c = threadIdx.x; c < CC; c += 128) { float x = p[c]; s += x; ss += x * x; }
    __shared__ float r1[128], r2[128];
    r1[threadIdx.x] = s; r2[threadIdx.x] = ss; __syncthreads();
    for (int o = 64; o > 0; o >>= 1) {
        if (threadIdx.x < o) { r1[threadIdx.x] += r1[threadIdx.x+o]; r2[threadIdx.x] += r2[threadIdx.x+o]; }
        __syncthreads();
    }
    if (threadIdx.x == 0) {
        float sum = r1[0], sq = r2[0];
        float mu = sum / CC;
        float var = sq / CC - mu * mu;
        d_mu[row] = mu;
        d_rs[row] = rsqrtf(var + 1e-5f);
        d_invn_img[row] = 1.f / fmaxf(sqrtf(sq), 1e-12f);
    }
}

// ---------------- global (mean-pooled, l2-normalized) embeddings --------
__global__ void kGloImg(const float* __restrict__ img) {
    int b = blockIdx.x; int c = threadIdx.x;  // 512 threads
    float acc = 0.f;
    for (int l = 0; l < LV; l++) acc += img[((size_t)b*LV + l)*CC + c];
    acc /= (float)LV;
    __shared__ float red[512];
    red[c] = acc * acc; __syncthreads();
    for (int o = 256; o > 0; o >>= 1) { if (c < o) red[c] += red[c+o]; __syncthreads(); }
    float n = fmaxf(sqrtf(red[0]), 1e-12f);
    d_imgglo[b*CC + c] = acc / n;
}

__global__ void kGloCap(const float* __restrict__ cap) {
    int b = blockIdx.x; int c = threadIdx.x;
    float acc = 0.f;
    for (int l = 0; l < NW; l++) acc += cap[((size_t)b*NW + l)*CC + c];
    acc /= (float)NW;
    __shared__ float red[512];
    red[c] = acc * acc; __syncthreads();
    for (int o = 256; o > 0; o >>= 1) { if (c < o) red[c] += red[c+o]; __syncthreads(); }
    float n = fmaxf(sqrtf(red[0]), 1e-12f);
    d_capglo[b*CC + c] = acc / n;
}

__global__ void kCapRow(const float* __restrict__ cap) {
    int row = blockIdx.x;  // t*NW + w
    const float* p = cap + (size_t)row * CC;
    float ss = 0.f;
    for (int c = threadIdx.x; c < CC; c += 128) { float x = p[c]; ss += x * x; }
    __shared__ float red[128];
    red[threadIdx.x] = ss; __syncthreads();
    for (int o = 64; o > 0; o >>= 1) { if (threadIdx.x < o) red[threadIdx.x] += red[threadIdx.x+o]; __syncthreads(); }
    if (threadIdx.x == 0) d_capinv[row] = 1.f / fmaxf(sqrtf(red[0]), 1e-12f);
}

// ---------------- score[t,v,l] = self_attn + cross_attn -----------------
__global__ void kScore(const float* __restrict__ img) {
    int l = blockIdx.x, v = blockIdx.y;
    __shared__ float row[CC];
    const float* p = img + ((size_t)v*LV + l)*CC;
    for (int c = threadIdx.x; c < CC; c += 128) row[c] = p[c];
    __syncthreads();
    int lane = threadIdx.x & 31, wid = threadIdx.x >> 5;
    float inv = d_invn_img[v*LV + l];
    float sp = 0.f;
    #pragma unroll
    for (int e = 0; e < 16; e++) { int c = lane + 32*e; sp += row[c] * d_imgglo[v*CC + c]; }
    for (int o = 16; o; o >>= 1) sp += __shfl_xor_sync(0xffffffffu, sp, o);
    for (int t = wid; t < BT; t += 4) {
        float cp = 0.f;
        #pragma unroll
        for (int e = 0; e < 16; e++) { int c = lane + 32*e; cp += row[c] * d_capglo[t*CC + c]; }
        for (int o = 16; o; o >>= 1) cp += __shfl_xor_sync(0xffffffffu, cp, o);
        if (lane == 0) d_score[((size_t)t*BV + v)*LV + l] = inv * (sp + cp);
    }
}

// ---------------- exact top-K partition via stable rank -----------------
__global__ void kSelect(float* __restrict__ out) {
    int t = blockIdx.x, v = blockIdx.y;
    int tv = t*BV + v;
    __shared__ float s[LV];
    __shared__ float red[256];
    int tid = threadIdx.x;
    if (tid < LV) s[tid] = d_score[(size_t)tv*LV + tid];
    __syncthreads();
    int cnt = 0; float sl = 0.f; bool keep = false;
    if (tid < LV) {
        sl = s[tid];
        for (int j = 0; j < LV; j++) {
            float sj = s[j];
            cnt += (sj > sl) || (sj == sl && j < tid);
        }
        keep = cnt < NK;
        out[OFFMASK + (size_t)tv*LV + tid] = keep ? 1.f : 0.f;
        if (keep) d_kidx[tv*NK + cnt] = tid;
    }
    // softmax over non-kept scores (order-invariant)
    red[tid] = (tid < LV && !keep) ? sl : -INFINITY;
    __syncthreads();
    for (int o = 128; o > 0; o >>= 1) { if (tid < o) red[tid] = fmaxf(red[tid], red[tid+o]); __syncthreads(); }
    float m = red[0];
    __syncthreads();
    float ev = (tid < LV && !keep) ? expf(sl - m) : 0.f;
    red[tid] = ev;
    __syncthreads();
    for (int o = 128; o > 0; o >>= 1) { if (tid < o) red[tid] += red[tid+o]; __syncthreads(); }
    float Z = red[0];
    if (tid < LV) d_wnon[(size_t)tv*LV + tid] = keep ? 0.f : ev / Z;
}

// ---------------- extra tokens: one block per v, all 32 t at once -------
__global__ void kExtra(const float* __restrict__ img) {
    int v = blockIdx.x;
    __shared__ float wn[BT*LV];
    int tid = threadIdx.x;
    for (int idx = tid; idx < BT*LV; idx += 256)
        wn[idx] = d_wnon[((size_t)(idx/LV)*BV + v)*LV + (idx % LV)];
    __syncthreads();
    #pragma unroll
    for (int half = 0; half < 2; half++) {
        int c = tid + 256*half;
        float acc[BT];
        #pragma unroll
        for (int t = 0; t < BT; t++) acc[t] = 0.f;
        for (int l = 0; l < LV; l++) {
            float x = img[((size_t)v*LV + l)*CC + c];
            #pragma unroll
            for (int t = 0; t < BT; t++) acc[t] += wn[t*LV + l] * x;
        }
        #pragma unroll
        for (int t = 0; t < BT; t++) d_extra[((size_t)t*BV + v)*CC + c] = acc[t];
    }
}

// ---------------- fold gamma/beta into W1 -------------------------------
__global__ void kPrepG1(const float* __restrict__ W1, const float* __restrict__ gamma) {
    int idx = blockIdx.x*256 + threadIdx.x;
    if (idx < CC*HH) { int c = idx / HH; d_G1[idx] = gamma[c] * W1[idx]; }
}

__global__ void kPrepCol(const float* __restrict__ W1, const float* __restrict__ beta,
                         const float* __restrict__ b1) {
    int h = blockIdx.x;
    float s1 = 0.f, s2 = 0.f;
    for (int c = threadIdx.x; c < CC; c += 128) {
        s1 += d_G1[c*HH + h];
        s2 += beta[c] * W1[c*HH + h];
    }
    __shared__ float r1[128], r2[128];
    r1[threadIdx.x] = s1; r2[threadIdx.x] = s2; __syncthreads();
    for (int o = 64; o > 0; o >>= 1) {
        if (threadIdx.x < o) { r1[threadIdx.x] += r1[threadIdx.x+o]; r2[threadIdx.x] += r2[threadIdx.x+o]; }
        __syncthreads();
    }
    if (threadIdx.x == 0) { d_cs[h] = r1[0]; d_bb[h] = r2[0] + b1[h]; }
}

// ---------------- kHL: LN-folded MLP -> logits (R5-proven FFMA2) --------
#define HL_FLOATS (6664 + 6732 + 10192 + 5096 + 102 + 102 + 98 + 98 + 49 + 1)
#define SMEM_HL (HL_FLOATS*4)

__global__ void kHL(const float* __restrict__ img, const float* __restrict__ W2,
                    const float* __restrict__ b2, const float* __restrict__ scale) {
    extern __shared__ float sm[];
    float* As   = sm;               // 98 x 68
    float* Gst  = As + 6664;        // 102 x 66 (transposed: [c][kk])
    float* Hs   = Gst + 6732;       // 98 x 104
    float* W2st = Hs + 10192;       // 49 x 104 (transposed: [p][h])
    float* css  = W2st + 5096;      // 102
    float* bbs  = css + 102;        // 102
    float* mus  = bbs + 102;        // 98
    float* rss  = mus + 98;         // 98
    float* b2s  = rss + 98;         // 49
    float* ssc  = b2s + 49;         // 1

    int v = blockIdx.x, l0 = blockIdx.y * NK;
    int tid = threadIdx.x; int tx = tid & 15, ty = tid >> 4;

    if (tid < NK) {
        int row = v*LV + l0 + tid;
        mus[tid] = d_mu[row];
        rss[tid] = d_rs[row];
    }
    if (tid < HH) { css[tid] = d_cs[tid]; bbs[tid] = d_bb[tid]; }
    if (tid < KP) b2s[tid] = b2[tid];
    if (tid == 0) ssc[0] = scale[0];
    __syncthreads();

    ull acc2[7][7];
    #pragma unroll
    for (int i = 0; i < 7; i++)
        #pragma unroll
        for (int j = 0; j < 7; j++) acc2[i][j] = 0ull;

    for (int k0 = 0; k0 < CC; k0 += 64) {
        for (int idx = tid; idx < NK*16; idx += 256) {
            int r = idx >> 4, q = (idx & 15) << 2;
            *(float4*)&As[r*68 + q] =
                *(const float4*)&img[((size_t)v*LV + l0 + r)*CC + k0 + q];
        }
        // Gst[c][kk] = G1[k0+kk][c], coalesced reads over c
        for (int idx = tid; idx < 64*HH; idx += 256) {
            int kk = idx / HH, c = idx % HH;
            Gst[c*66 + kk] = d_G1[(k0 + kk)*HH + c];
        }
        __syncthreads();
        #pragma unroll 4
        for (int kk = 0; kk < 64; kk += 2) {
            ull a2[7], b2r[7];
            #pragma unroll
            for (int i = 0; i < 7; i++) { int r = ty + 16*i; if (r > 97) r = 97; a2[i] = *(const ull*)&As[r*68 + kk]; }
            #pragma unroll
            for (int j = 0; j < 7; j++) { int c = tx + 16*j; if (c > 101) c = 101; b2r[j] = *(const ull*)&Gst[c*66 + kk]; }
            #pragma unroll
            for (int i = 0; i < 7; i++)
                #pragma unroll
                for (int j = 0; j < 7; j++) FMA2(acc2[i][j], a2[i], b2r[j]);
        }
        __syncthreads();
    }

    // epilogue: LN fold + exact gelu -> Hs
    #pragma unroll
    for (int i = 0; i < 7; i++) {
        int r = ty + 16*i;
        if (r < NK) {
            float mu = mus[r], rsg = rss[r];
            #pragma unroll
            for (int j = 0; j < 7; j++) {
                int c = tx + 16*j;
                if (c < HH) {
                    float x = rsg * (sum2(acc2[i][j]) - mu * css[c]) + bbs[c];
                    Hs[r*104 + c] = 0.5f * x * (1.f + erff(x * 0.70710678118654752f));
                }
            }
        }
    }
    // W2st[p][h] = W2[h][p]
    for (int idx = tid; idx < HH*KP; idx += 256) {
        int p = idx / HH, h = idx % HH;
        W2st[p*104 + h] = W2[h*KP + p];
    }
    __syncthreads();

    float sc = ssc[0];
    for (int idx = tid; idx < NK*KP; idx += 256) {
        int r = idx / KP, p = idx % KP;
        ull a2 = 0ull;
        #pragma unroll 4
        for (int h = 0; h < HH; h += 2)
            FMA2(a2, *(const ull*)&Hs[r*104 + h], *(const ull*)&W2st[p*104 + h]);
        d_L[((size_t)v*LV + l0 + r)*KP + p] = sc * (b2s[p] + sum2(a2));
    }
}

// ---------------- E2: phase B FFMA2 + phase C on 250 threads ------------
#define OFF_WWT  0
#define OFF_SCT  5600
#define OFF_AT   12400
#define OFF_CPT  16208
#define OFF_GR   17840
#define OFF_SR   20440
#define OFF_AP   21688
#define OFF_EW   22936
#define OFF_INV  24184
#define OFF_DTS  24236
#define OFF_WSM  24260
#define OFF_KIX  24284
#define SMEM_E2  ((24284 + 98) * 4)

__global__ void __launch_bounds__(256, 2)
kE2(const float* __restrict__ img, const float* __restrict__ cap,
    float* __restrict__ out) {
    extern __shared__ float sm[];
    float* WWt = sm + OFF_WWT;   // [k=0..99][p=0..55] k-major softmax weights
    float* SCt = sm + OFF_SCT;   // [k=0..99][c=0..67] gathered tokens (c-tile)
    float* At  = sm + OFF_AT;    // [p=0..55][c=0..67] aggr tokens (49) + extra (row 49) + zeros
    float* CPt = sm + OFF_CPT;   // [w=0..23][c=0..67] normalized caption words
    float* Gr  = sm + OFF_GR;    // 50 x 52
    float* Sr  = sm + OFF_SR;    // 24 x 52
    float* Ap  = sm + OFF_AP;    // 24 x 52
    float* Ew  = sm + OFF_EW;    // 24 x 52
    float* invn= sm + OFF_INV;   // 52
    float* dts = sm + OFF_DTS;   // 24
    float* wsm = sm + OFF_WSM;   // 24
    int*   kix = (int*)(sm + OFF_KIX);

    int t = blockIdx.x, v = blockIdx.y; int tv = t*BV + v;
    int tid = threadIdx.x;

    // ---- init: kix, zero pads ----
    if (tid < NK) kix[tid] = d_kidx[tv*NK + tid];
    for (int i = tid; i < 2*68; i += 256) SCt[98*68 + i] = 0.f;
    for (int i = tid; i < 6*68; i += 256) At[50*68 + i] = 0.f;
    for (int i = tid; i < 2*56; i += 256) WWt[98*56 + i] = 0.f;
    __syncthreads();

    // ---- gather logits (transposed, k-major) ----
    for (int idx = tid; idx < NK*KP; idx += 256) {
        int k = idx / KP, p = idx % KP;
        WWt[k*56 + p] = d_L[((size_t)v*LV + kix[k])*KP + p];
    }
    for (int idx = tid; idx < NK*7; idx += 256) {   // pad cols 49..55
        int k = idx / 7, p = 49 + idx % 7;
        WWt[k*56 + p] = 0.f;
    }
    __syncthreads();
    // softmax over k per p (column-wise, in place)
    if (tid < KP) {
        float m = -INFINITY;
        for (int k = 0; k < NK; k++) m = fmaxf(m, WWt[k*56 + tid]);
        float Z = 0.f;
        for (int k = 0; k < NK; k++) { float e = expf(WWt[k*56 + tid] - m); WWt[k*56 + tid] = e; Z += e; }
        float iz = 1.f / Z;
        for (int k = 0; k < NK; k++) WWt[k*56 + tid] *= iz;
    }
    __syncthreads();

    // ---- phase-C role assignment (250 threads, single union pattern) ----
    bool doC = tid < 250;
    bool isGram = tid < 175;
    int rA0 = 0, rB0 = 0, strB = 7;
    const float* Bbase = At;
    if (isGram)   { rA0 = tid / 7;       rB0 = tid % 7; strB = 7; Bbase = At;  }
    else if (doC) { int s = tid - 175;   rA0 = s / 3;   rB0 = s % 3; strB = 3; Bbase = CPt; }
    float accC[2][8];
    #pragma unroll
    for (int i = 0; i < 2; i++)
        #pragma unroll
        for (int j = 0; j < 8; j++) accC[i][j] = 0.f;

    int pt = tid >> 4;      // phase B: 0..15, active <13
    int ct = tid & 15;

    for (int c0 = 0; c0 < CC; c0 += 64) {
        // ---- phase A: loads ----
        for (int idx = tid; idx < NK*16; idx += 256) {
            int r = idx >> 4, q = idx & 15;
            *(float4*)&SCt[r*68 + (q<<2)] =
                *(const float4*)&img[((size_t)v*LV + kix[r])*CC + c0 + (q<<2)];
        }
        for (int idx = tid; idx < NW*16; idx += 256) {
            int w = idx >> 4, q = idx & 15;
            float4 x = *(const float4*)&cap[((size_t)t*NW + w)*CC + c0 + (q<<2)];
            float iv = d_capinv[t*NW + w];
            x.x *= iv; x.y *= iv; x.z *= iv; x.w *= iv;
            *(float4*)&CPt[w*68 + (q<<2)] = x;
        }
        if (tid < 16)
            *(float4*)&At[49*68 + (tid<<2)] =
                *(const float4*)&d_extra[(size_t)tv*CC + c0 + (tid<<2)];
        __syncthreads();

        // ---- phase B: aggr (FFMA2 over c-pairs; w scalar dup'd) ----
        if (pt < 13) {
            ull c00=0,c01=0,c10=0,c11=0,c20=0,c21=0,c30=0,c31=0;
            #pragma unroll 4
            for (int k = 0; k < 100; k++) {
                float4 w = *(const float4*)&WWt[k*56 + (pt<<2)];
                ulonglong2 s = *(const ulonglong2*)&SCt[k*68 + (ct<<2)];
                ull w0 = dup2(w.x), w1 = dup2(w.y), w2 = dup2(w.z), w3 = dup2(w.w);
                FMA2(c00, w0, s.x); FMA2(c01, w0, s.y);
                FMA2(c10, w1, s.x); FMA2(c11, w1, s.y);
                FMA2(c20, w2, s.x); FMA2(c21, w2, s.y);
                FMA2(c30, w3, s.x); FMA2(c31, w3, s.y);
            }
            int p = pt << 2;
            if (p     < KP) { *(ull*)&At[(p  )*68 + (ct<<2)] = c00; *(ull*)&At[(p  )*68 + (ct<<2) + 2] = c01; }
            if (p + 1 < KP) { *(ull*)&At[(p+1)*68 + (ct<<2)] = c10; *(ull*)&At[(p+1)*68 + (ct<<2) + 2] = c11; }
            if (p + 2 < KP) { *(ull*)&At[(p+2)*68 + (ct<<2)] = c20; *(ull*)&At[(p+2)*68 + (ct<<2) + 2] = c21; }
            if (p + 3 < KP) { *(ull*)&At[(p+3)*68 + (ct<<2)] = c30; *(ull*)&At[(p+3)*68 + (ct<<2) + 2] = c31; }
        }
        __syncthreads();

        // ---- phase C: Gram / Sr accumulation (single union loop, scalar) ----
        if (doC) {
            #pragma unroll
            for (int c4 = 0; c4 < 16; c4++) {
                float4 a0 = *(const float4*)&At[rA0*68 + (c4<<2)];
                float4 a1 = *(const float4*)&At[(rA0 + 25)*68 + (c4<<2)];
                #pragma unroll
                for (int j = 0; j < 8; j++) {
                    float4 b = *(const float4*)&Bbase[(rB0 + strB*j)*68 + (c4<<2)];
                    accC[0][j] += a0.x*b.x + a0.y*b.y + a0.z*b.z + a0.w*b.w;
                    accC[1][j] += a1.x*b.x + a1.y*b.y + a1.z*b.z + a1.w*b.w;
                }
            }
        }
        __syncthreads();
    }

    // ---- dump Gram / Sr to smem ----
    if (isGram) {
        #pragma unroll
        for (int i = 0; i < 2; i++) {
            int p = rA0 + 25*i;
            #pragma unroll
            for (int j = 0; j < 8; j++) {
                int q = rB0 + 7*j;
                if (q < 50) Gr[p*52 + q] = accC[i][j];
            }
        }
    } else if (doC) {
        #pragma unroll
        for (int i = 0; i < 2; i++) {
            int q = rA0 + 25*i;
            #pragma unroll
            for (int j = 0; j < 8; j++) {
                int w = rB0 + 3*j;
                Sr[w*52 + q] = accC[i][j];
            }
        }
    }
    __syncthreads();

    // ---- finalize: invn from Gram diagonal ----
    if (tid < 50) invn[tid] = 1.f / fmaxf(sqrtf(fmaxf(Gr[tid*52 + tid], 0.f)), 1e-12f);
    __syncthreads();

    // ---- per-word softmax over 50 tokens + dt ----
    if (tid < NW) {
        int w = tid;
        float m = -INFINITY;
        for (int p = 0; p < 50; p++) m = fmaxf(m, invn[p] * Sr[w*52 + p]);
        m *= 4.f;
        float Z = 0.f;
        for (int p = 0; p < 50; p++) {
            float e = expf(4.f * invn[p] * Sr[w*52 + p] - m);
            Ew[w*52 + p] = e; Z += e;
        }
        float iz = 1.f / Z;
        float dt = 0.f;
        for (int p = 0; p < 50; p++) {
            float ap = Ew[w*52 + p] * iz * invn[p];   // attn * invn
            Ap[w*52 + p] = ap;
            dt += ap * Sr[w*52 + p];
        }
        dts[w] = dt;
    }
    __syncthreads();
    // ---- y[w,q] = sum_p Ap[w,p] * Gr[p,q]  (into Ew scratch) ----
    for (int idx = tid; idx < NW*50; idx += 256) {
        int w = idx / 50, q = idx % 50;
        float s = 0.f;
        for (int p = 0; p < 50; p++) s += Ap[w*52 + p] * Gr[p*52 + q];
        Ew[w*52 + q] = s;
    }
    __syncthreads();
    if (tid < NW) {
        float ss = 0.f;
        for (int q = 0; q < 50; q++) ss += Ap[tid*52 + q] * Ew[tid*52 + q];
        wsm[tid] = dts[tid] / fmaxf(sqrtf(fmaxf(ss, 0.f)), 1e-12f);
    }
    __syncthreads();
    if (tid == 0) {
        float s = 0.f;
        for (int w = 0; w < NW; w++) s += wsm[w];
        out[v*BT + t] = s / (float)NW;   // improve_sims = sim.T
    }
}

// ------------------------------ launch ----------------------------------
extern "C" void kernel_launch(void* const* d_in, const int* in_sizes, int n_in,
                              void* d_out, int out_size) {
    const float* img   = (const float*)d_in[0];
    const float* cap   = (const float*)d_in[1];
    // d_in[2] = cap_lens (unused by reference math)
    const float* gamma = (const float*)d_in[3];
    const float* beta  = (const float*)d_in[4];
    const float* W1    = (const float*)d_in[5];
    const float* b1    = (const float*)d_in[6];
    const float* W2    = (const float*)d_in[7];
    const float* b2    = (const float*)d_in[8];
    const float* scale = (const float*)d_in[9];
    float* out = (float*)d_out;

    kRowStats<<<BV*LV, 128>>>(img);
    kGloImg<<<BV, 512>>>(img);
    kGloCap<<<BT, 512>>>(cap);
    kCapRow<<<BT*NW, 128>>>(cap);
    kScore<<<dim3(LV, BV), 128>>>(img);
    kSelect<<<dim3(BT, BV), 256>>>(out);
    kExtra<<<BV, 256>>>(img);
    kPrepG1<<<(CC*HH + 255)/256, 256>>>(W1, gamma);
    kPrepCol<<<HH, 128>>>(W1, beta, b1);

    cudaFuncSetAttribute(kHL, cudaFuncAttributeMaxDynamicSharedMemorySize, SMEM_HL);
    kHL<<<dim3(BV, 2), 256, SMEM_HL>>>(img, W2, b2, scale);

    cudaFuncSetAttribute(kE2, cudaFuncAttributeMaxDynamicSharedMemorySize, SMEM_E2);
    kE2<<<dim3(BT, BV), 256, SMEM_E2>>>(img, cap, out);
}

// round 16
// speedup vs baseline: 1.0064x; 1.0064x over previous
#include <cuda_runtime.h>
#include <math.h>

#define CC 512
#define LV 196
#define BV 64
#define BT 32
#define NW 24
#define NK 98
#define KP 49
#define HH 102
#define OFFMASK (BV*BT)

typedef unsigned long long ull;

#define FMA2(d, a, b) asm("fma.rn.f32x2 %0, %1, %2, %0;" : "+l"(d) : "l"(a), "l"(b))
__device__ __forceinline__ ull dup2(float w) {
    ull r;
    asm("mov.b64 %0, {%1, %1};" : "=l"(r) : "r"(__float_as_uint(w)));
    return r;
}

// ---------------- device scratch (no allocation allowed) ----------------
__device__ float d_mu[BV*LV];
__device__ float d_rs[BV*LV];
__device__ float d_invn_img[BV*LV];
__device__ float d_imgglo[BV*CC];
__device__ float d_capglo[BT*CC];
__device__ float d_capinv[BT*NW];
__device__ float d_score[BT*BV*LV];
__device__ int   d_kidx[BT*BV*NK];
__device__ float d_wnon[BT*BV*LV];
__device__ float d_extra[BT*BV*CC];
__device__ float d_G1[CC*HH];
__device__ float d_cs[HH];
__device__ float d_bb[HH];
__device__ float d_L[BV*LV*KP];   // precomputed (scaled) logits per (v,l,p)

// ---------------- row stats for img: mean, rsigma(LN), inv l2 norm ------
__global__ void kRowStats(const float* __restrict__ img) {
    int row = blockIdx.x;  // v*LV + l
    const float* p = img + (size_t)row * CC;
    float s = 0.f, ss = 0.f;
    for (int c = threadIdx.x; c < CC; c += 128) { float x = p[c]; s += x; ss += x * x; }
    __shared__ float r1[128], r2[128];
    r1[threadIdx.x] = s; r2[threadIdx.x] = ss; __syncthreads();
    for (int o = 64; o > 0; o >>= 1) {
        if (threadIdx.x < o) { r1[threadIdx.x] += r1[threadIdx.x+o]; r2[threadIdx.x] += r2[threadIdx.x+o]; }
        __syncthreads();
    }
    if (threadIdx.x == 0) {
        float sum = r1[0], sq = r2[0];
        float mu = sum / CC;
        float var = sq / CC - mu * mu;
        d_mu[row] = mu;
        d_rs[row] = rsqrtf(var + 1e-5f);
        d_invn_img[row] = 1.f / fmaxf(sqrtf(sq), 1e-12f);
    }
}

// ---------------- global (mean-pooled, l2-normalized) embeddings --------
__global__ void kGloImg(const float* __restrict__ img) {
    int b = blockIdx.x; int c = threadIdx.x;  // 512 threads
    float acc = 0.f;
    for (int l = 0; l < LV; l++) acc += img[((size_t)b*LV + l)*CC + c];
    acc /= (float)LV;
    __shared__ float red[512];
    red[c] = acc * acc; __syncthreads();
    for (int o = 256; o > 0; o >>= 1) { if (c < o) red[c] += red[c+o]; __syncthreads(); }
    float n = fmaxf(sqrtf(red[0]), 1e-12f);
    d_imgglo[b*CC + c] = acc / n;
}

__global__ void kGloCap(const float* __restrict__ cap) {
    int b = blockIdx.x; int c = threadIdx.x;
    float acc = 0.f;
    for (int l = 0; l < NW; l++) acc += cap[((size_t)b*NW + l)*CC + c];
    acc /= (float)NW;
    __shared__ float red[512];
    red[c] = acc * acc; __syncthreads();
    for (int o = 256; o > 0; o >>= 1) { if (c < o) red[c] += red[c+o]; __syncthreads(); }
    float n = fmaxf(sqrtf(red[0]), 1e-12f);
    d_capglo[b*CC + c] = acc / n;
}

__global__ void kCapRow(const float* __restrict__ cap) {
    int row = blockIdx.x;  // t*NW + w
    const float* p = cap + (size_t)row * CC;
    float ss = 0.f;
    for (int c = threadIdx.x; c < CC; c += 128) { float x = p[c]; ss += x * x; }
    __shared__ float red[128];
    red[threadIdx.x] = ss; __syncthreads();
    for (int o = 64; o > 0; o >>= 1) { if (threadIdx.x < o) red[threadIdx.x] += red[threadIdx.x+o]; __syncthreads(); }
    if (threadIdx.x == 0) d_capinv[row] = 1.f / fmaxf(sqrtf(red[0]), 1e-12f);
}

// ---------------- score[t,v,l] = self_attn + cross_attn -----------------
__global__ void kScore(const float* __restrict__ img) {
    int l = blockIdx.x, v = blockIdx.y;
    __shared__ float row[CC];
    const float* p = img + ((size_t)v*LV + l)*CC;
    for (int c = threadIdx.x; c < CC; c += 128) row[c] = p[c];
    __syncthreads();
    int lane = threadIdx.x & 31, wid = threadIdx.x >> 5;
    float inv = d_invn_img[v*LV + l];
    float sp = 0.f;
    #pragma unroll
    for (int e = 0; e < 16; e++) { int c = lane + 32*e; sp += row[c] * d_imgglo[v*CC + c]; }
    for (int o = 16; o; o >>= 1) sp += __shfl_xor_sync(0xffffffffu, sp, o);
    for (int t = wid; t < BT; t += 4) {
        float cp = 0.f;
        #pragma unroll
        for (int e = 0; e < 16; e++) { int c = lane + 32*e; cp += row[c] * d_capglo[t*CC + c]; }
        for (int o = 16; o; o >>= 1) cp += __shfl_xor_sync(0xffffffffu, cp, o);
        if (lane == 0) d_score[((size_t)t*BV + v)*LV + l] = inv * (sp + cp);
    }
}

// ---------------- exact top-K partition via stable rank -----------------
__global__ void kSelect(float* __restrict__ out) {
    int t = blockIdx.x, v = blockIdx.y;
    int tv = t*BV + v;
    __shared__ float s[LV];
    __shared__ float red[256];
    int tid = threadIdx.x;
    if (tid < LV) s[tid] = d_score[(size_t)tv*LV + tid];
    __syncthreads();
    int cnt = 0; float sl = 0.f; bool keep = false;
    if (tid < LV) {
        sl = s[tid];
        for (int j = 0; j < LV; j++) {
            float sj = s[j];
            cnt += (sj > sl) || (sj == sl && j < tid);
        }
        keep = cnt < NK;
        out[OFFMASK + (size_t)tv*LV + tid] = keep ? 1.f : 0.f;
        if (keep) d_kidx[tv*NK + cnt] = tid;
    }
    // softmax over non-kept scores (order-invariant)
    red[tid] = (tid < LV && !keep) ? sl : -INFINITY;
    __syncthreads();
    for (int o = 128; o > 0; o >>= 1) { if (tid < o) red[tid] = fmaxf(red[tid], red[tid+o]); __syncthreads(); }
    float m = red[0];
    __syncthreads();
    float ev = (tid < LV && !keep) ? expf(sl - m) : 0.f;
    red[tid] = ev;
    __syncthreads();
    for (int o = 128; o > 0; o >>= 1) { if (tid < o) red[tid] += red[tid+o]; __syncthreads(); }
    float Z = red[0];
    if (tid < LV) d_wnon[(size_t)tv*LV + tid] = keep ? 0.f : ev / Z;
}

// ---------------- extra tokens: one block per v, all 32 t at once -------
__global__ void kExtra(const float* __restrict__ img) {
    int v = blockIdx.x;
    __shared__ float wn[BT*LV];
    int tid = threadIdx.x;
    for (int idx = tid; idx < BT*LV; idx += 256)
        wn[idx] = d_wnon[((size_t)(idx/LV)*BV + v)*LV + (idx % LV)];
    __syncthreads();
    #pragma unroll
    for (int half = 0; half < 2; half++) {
        int c = tid + 256*half;
        float acc[BT];
        #pragma unroll
        for (int t = 0; t < BT; t++) acc[t] = 0.f;
        for (int l = 0; l < LV; l++) {
            float x = img[((size_t)v*LV + l)*CC + c];
            #pragma unroll
            for (int t = 0; t < BT; t++) acc[t] += wn[t*LV + l] * x;
        }
        #pragma unroll
        for (int t = 0; t < BT; t++) d_extra[((size_t)t*BV + v)*CC + c] = acc[t];
    }
}

// ---------------- fold gamma/beta into W1 -------------------------------
__global__ void kPrepG1(const float* __restrict__ W1, const float* __restrict__ gamma) {
    int idx = blockIdx.x*256 + threadIdx.x;
    if (idx < CC*HH) { int c = idx / HH; d_G1[idx] = gamma[c] * W1[idx]; }
}

__global__ void kPrepCol(const float* __restrict__ W1, const float* __restrict__ beta,
                         const float* __restrict__ b1) {
    int h = blockIdx.x;
    float s1 = 0.f, s2 = 0.f;
    for (int c = threadIdx.x; c < CC; c += 128) {
        s1 += d_G1[c*HH + h];
        s2 += beta[c] * W1[c*HH + h];
    }
    __shared__ float r1[128], r2[128];
    r1[threadIdx.x] = s1; r2[threadIdx.x] = s2; __syncthreads();
    for (int o = 64; o > 0; o >>= 1) {
        if (threadIdx.x < o) { r1[threadIdx.x] += r1[threadIdx.x+o]; r2[threadIdx.x] += r2[threadIdx.x+o]; }
        __syncthreads();
    }
    if (threadIdx.x == 0) { d_cs[h] = r1[0]; d_bb[h] = r2[0] + b1[h]; }
}

// ---------------- kHL: per (v, row-half) LN-folded MLP -> logits --------
#define HL_FLOATS (6664 + 6656 + 10192 + 5304 + 102 + 102 + 98 + 98 + 49 + 1)
#define SMEM_HL (HL_FLOATS*4)

__global__ void kHL(const float* __restrict__ img, const float* __restrict__ W2,
                    const float* __restrict__ b2, const float* __restrict__ scale) {
    extern __shared__ float sm[];
    float* As  = sm;               // 98 x 68
    float* Gs  = As + 6664;        // 64 x 104
    float* Hs  = Gs + 6656;        // 98 x 104
    float* W2s = Hs + 10192;       // 102 x 52
    float* css = W2s + 5304;       // 102
    float* bbs = css + 102;        // 102
    float* mus = bbs + 102;        // 98
    float* rss = mus + 98;         // 98
    float* b2s = rss + 98;         // 49
    float* ssc = b2s + 49;         // 1

    int v = blockIdx.x, l0 = blockIdx.y * NK;
    int tid = threadIdx.x; int tx = tid & 15, ty = tid >> 4;

    if (tid < NK) {
        int row = v*LV + l0 + tid;
        mus[tid] = d_mu[row];
        rss[tid] = d_rs[row];
    }
    if (tid < HH) { css[tid] = d_cs[tid]; bbs[tid] = d_bb[tid]; }
    if (tid < KP) b2s[tid] = b2[tid];
    if (tid == 0) ssc[0] = scale[0];
    __syncthreads();

    float acc[7][7];
    #pragma unroll
    for (int i = 0; i < 7; i++)
        #pragma unroll
        for (int j = 0; j < 7; j++) acc[i][j] = 0.f;

    for (int k0 = 0; k0 < CC; k0 += 64) {
        for (int idx = tid; idx < NK*16; idx += 256) {
            int r = idx >> 4, q = (idx & 15) << 2;
            *(float4*)&As[r*68 + q] =
                *(const float4*)&img[((size_t)v*LV + l0 + r)*CC + k0 + q];
        }
        for (int idx = tid; idx < 64*HH; idx += 256) {
            int rr = idx / HH, c = idx % HH;
            Gs[rr*104 + c] = d_G1[(k0 + rr)*HH + c];
        }
        __syncthreads();
        #pragma unroll 4
        for (int kk = 0; kk < 64; kk++) {
            float a[7], b[7];
            #pragma unroll
            for (int i = 0; i < 7; i++) { int r = ty + 16*i; if (r > 97) r = 97; a[i] = As[r*68 + kk]; }
            #pragma unroll
            for (int j = 0; j < 7; j++) { int c = tx + 16*j; if (c > 101) c = 101; b[j] = Gs[kk*104 + c]; }
            #pragma unroll
            for (int i = 0; i < 7; i++)
                #pragma unroll
                for (int j = 0; j < 7; j++) acc[i][j] += a[i] * b[j];
        }
        __syncthreads();
    }

    #pragma unroll
    for (int i = 0; i < 7; i++) {
        int r = ty + 16*i;
        if (r < NK) {
            float mu = mus[r], rsg = rss[r];
            #pragma unroll
            for (int j = 0; j < 7; j++) {
                int c = tx + 16*j;
                if (c < HH) {
                    float x = rsg * (acc[i][j] - mu * css[c]) + bbs[c];
                    Hs[r*104 + c] = 0.5f * x * (1.f + erff(x * 0.70710678118654752f));
                }
            }
        }
    }
    for (int idx = tid; idx < HH*KP; idx += 256) {
        int h = idx / KP, p = idx % KP;
        W2s[h*52 + p] = W2[idx];
    }
    __syncthreads();

    float sc = ssc[0];
    for (int idx = tid; idx < NK*KP; idx += 256) {
        int r = idx / KP, p = idx % KP;
        float a2 = b2s[p];
        for (int h = 0; h < HH; h++) a2 += Hs[r*104 + h] * W2s[h*52 + p];
        d_L[((size_t)v*LV + l0 + r)*KP + p] = sc * a2;
    }
}

// ---------------- E2: phase B FFMA2 + phase C on 250 threads ------------
#define OFF_WWT  0
#define OFF_SCT  5600
#define OFF_AT   12400
#define OFF_CPT  16208
#define OFF_GR   17840
#define OFF_SR   20440
#define OFF_AP   21688
#define OFF_EW   22936
#define OFF_INV  24184
#define OFF_DTS  24236
#define OFF_WSM  24260
#define OFF_KIX  24284
#define SMEM_E2  ((24284 + 98) * 4)

__global__ void __launch_bounds__(256, 2)
kE2(const float* __restrict__ img, const float* __restrict__ cap,
    float* __restrict__ out) {
    extern __shared__ float sm[];
    float* WWt = sm + OFF_WWT;   // [k=0..99][p=0..55] k-major softmax weights
    float* SCt = sm + OFF_SCT;   // [k=0..99][c=0..67] gathered tokens (c-tile)
    float* At  = sm + OFF_AT;    // [p=0..55][c=0..67] aggr tokens (49) + extra (row 49) + zeros
    float* CPt = sm + OFF_CPT;   // [w=0..23][c=0..67] normalized caption words
    float* Gr  = sm + OFF_GR;    // 50 x 52
    float* Sr  = sm + OFF_SR;    // 24 x 52
    float* Ap  = sm + OFF_AP;    // 24 x 52
    float* Ew  = sm + OFF_EW;    // 24 x 52
    float* invn= sm + OFF_INV;   // 52
    float* dts = sm + OFF_DTS;   // 24
    float* wsm = sm + OFF_WSM;   // 24
    int*   kix = (int*)(sm + OFF_KIX);

    int t = blockIdx.x, v = blockIdx.y; int tv = t*BV + v;
    int tid = threadIdx.x;

    // ---- init: kix, zero pads ----
    if (tid < NK) kix[tid] = d_kidx[tv*NK + tid];
    for (int i = tid; i < 2*68; i += 256) SCt[98*68 + i] = 0.f;
    for (int i = tid; i < 6*68; i += 256) At[50*68 + i] = 0.f;
    for (int i = tid; i < 2*56; i += 256) WWt[98*56 + i] = 0.f;
    __syncthreads();

    // ---- gather logits (transposed, k-major) ----
    for (int idx = tid; idx < NK*KP; idx += 256) {
        int k = idx / KP, p = idx % KP;
        WWt[k*56 + p] = d_L[((size_t)v*LV + kix[k])*KP + p];
    }
    for (int idx = tid; idx < NK*7; idx += 256) {   // pad cols 49..55
        int k = idx / 7, p = 49 + idx % 7;
        WWt[k*56 + p] = 0.f;
    }
    __syncthreads();
    // softmax over k per p (column-wise, in place)
    if (tid < KP) {
        float m = -INFINITY;
        for (int k = 0; k < NK; k++) m = fmaxf(m, WWt[k*56 + tid]);
        float Z = 0.f;
        for (int k = 0; k < NK; k++) { float e = expf(WWt[k*56 + tid] - m); WWt[k*56 + tid] = e; Z += e; }
        float iz = 1.f / Z;
        for (int k = 0; k < NK; k++) WWt[k*56 + tid] *= iz;
    }
    __syncthreads();

    // ---- phase-C role assignment (250 threads, single union pattern) ----
    bool doC = tid < 250;
    bool isGram = tid < 175;
    int rA0 = 0, rB0 = 0, strB = 7;
    const float* Bbase = At;
    if (isGram)   { rA0 = tid / 7;       rB0 = tid % 7; strB = 7; Bbase = At;  }
    else if (doC) { int s = tid - 175;   rA0 = s / 3;   rB0 = s % 3; strB = 3; Bbase = CPt; }
    float accC[2][8];
    #pragma unroll
    for (int i = 0; i < 2; i++)
        #pragma unroll
        for (int j = 0; j < 8; j++) accC[i][j] = 0.f;

    int pt = tid >> 4;      // phase B: 0..15, active <13
    int ct = tid & 15;

    for (int c0 = 0; c0 < CC; c0 += 64) {
        // ---- phase A: loads ----
        for (int idx = tid; idx < NK*16; idx += 256) {
            int r = idx >> 4, q = idx & 15;
            *(float4*)&SCt[r*68 + (q<<2)] =
                *(const float4*)&img[((size_t)v*LV + kix[r])*CC + c0 + (q<<2)];
        }
        for (int idx = tid; idx < NW*16; idx += 256) {
            int w = idx >> 4, q = idx & 15;
            float4 x = *(const float4*)&cap[((size_t)t*NW + w)*CC + c0 + (q<<2)];
            float iv = d_capinv[t*NW + w];
            x.x *= iv; x.y *= iv; x.z *= iv; x.w *= iv;
            *(float4*)&CPt[w*68 + (q<<2)] = x;
        }
        if (tid < 16)
            *(float4*)&At[49*68 + (tid<<2)] =
                *(const float4*)&d_extra[(size_t)tv*CC + c0 + (tid<<2)];
        __syncthreads();

        // ---- phase B: aggr (FFMA2 over c-pairs; w scalar dup'd) ----
        if (pt < 13) {
            ull c00=0,c01=0,c10=0,c11=0,c20=0,c21=0,c30=0,c31=0;
            #pragma unroll 4
            for (int k = 0; k < 100; k++) {
                float4 w = *(const float4*)&WWt[k*56 + (pt<<2)];
                ulonglong2 s = *(const ulonglong2*)&SCt[k*68 + (ct<<2)];
                ull w0 = dup2(w.x), w1 = dup2(w.y), w2 = dup2(w.z), w3 = dup2(w.w);
                FMA2(c00, w0, s.x); FMA2(c01, w0, s.y);
                FMA2(c10, w1, s.x); FMA2(c11, w1, s.y);
                FMA2(c20, w2, s.x); FMA2(c21, w2, s.y);
                FMA2(c30, w3, s.x); FMA2(c31, w3, s.y);
            }
            int p = pt << 2;
            if (p     < KP) { *(ull*)&At[(p  )*68 + (ct<<2)] = c00; *(ull*)&At[(p  )*68 + (ct<<2) + 2] = c01; }
            if (p + 1 < KP) { *(ull*)&At[(p+1)*68 + (ct<<2)] = c10; *(ull*)&At[(p+1)*68 + (ct<<2) + 2] = c11; }
            if (p + 2 < KP) { *(ull*)&At[(p+2)*68 + (ct<<2)] = c20; *(ull*)&At[(p+2)*68 + (ct<<2) + 2] = c21; }
            if (p + 3 < KP) { *(ull*)&At[(p+3)*68 + (ct<<2)] = c30; *(ull*)&At[(p+3)*68 + (ct<<2) + 2] = c31; }
        }
        __syncthreads();

        // ---- phase C: Gram / Sr accumulation (single union loop, scalar) ----
        if (doC) {
            #pragma unroll
            for (int c4 = 0; c4 < 16; c4++) {
                float4 a0 = *(const float4*)&At[rA0*68 + (c4<<2)];
                float4 a1 = *(const float4*)&At[(rA0 + 25)*68 + (c4<<2)];
                #pragma unroll
                for (int j = 0; j < 8; j++) {
                    float4 b = *(const float4*)&Bbase[(rB0 + strB*j)*68 + (c4<<2)];
                    accC[0][j] += a0.x*b.x + a0.y*b.y + a0.z*b.z + a0.w*b.w;
                    accC[1][j] += a1.x*b.x + a1.y*b.y + a1.z*b.z + a1.w*b.w;
                }
            }
        }
        __syncthreads();
    }

    // ---- dump Gram / Sr to smem ----
    if (isGram) {
        #pragma unroll
        for (int i = 0; i < 2; i++) {
            int p = rA0 + 25*i;
            #pragma unroll
            for (int j = 0; j < 8; j++) {
                int q = rB0 + 7*j;
                if (q < 50) Gr[p*52 + q] = accC[i][j];
            }
        }
    } else if (doC) {
        #pragma unroll
        for (int i = 0; i < 2; i++) {
            int q = rA0 + 25*i;
            #pragma unroll
            for (int j = 0; j < 8; j++) {
                int w = rB0 + 3*j;
                Sr[w*52 + q] = accC[i][j];
            }
        }
    }
    __syncthreads();

    // ---- finalize: invn from Gram diagonal ----
    if (tid < 50) invn[tid] = 1.f / fmaxf(sqrtf(fmaxf(Gr[tid*52 + tid], 0.f)), 1e-12f);
    __syncthreads();

    // ---- per-word softmax over 50 tokens + dt ----
    if (tid < NW) {
        int w = tid;
        float m = -INFINITY;
        for (int p = 0; p < 50; p++) m = fmaxf(m, invn[p] * Sr[w*52 + p]);
        m *= 4.f;
        float Z = 0.f;
        for (int p = 0; p < 50; p++) {
            float e = expf(4.f * invn[p] * Sr[w*52 + p] - m);
            Ew[w*52 + p] = e; Z += e;
        }
        float iz = 1.f / Z;
        float dt = 0.f;
        for (int p = 0; p < 50; p++) {
            float ap = Ew[w*52 + p] * iz * invn[p];   // attn * invn
            Ap[w*52 + p] = ap;
            dt += ap * Sr[w*52 + p];
        }
        dts[w] = dt;
    }
    __syncthreads();
    // ---- y[w,q] = sum_p Ap[w,p] * Gr[p,q]  (into Ew scratch) ----
    for (int idx = tid; idx < NW*50; idx += 256) {
        int w = idx / 50, q = idx % 50;
        float s = 0.f;
        for (int p = 0; p < 50; p++) s += Ap[w*52 + p] * Gr[p*52 + q];
        Ew[w*52 + q] = s;
    }
    __syncthreads();
    if (tid < NW) {
        float ss = 0.f;
        for (int q = 0; q < 50; q++) ss += Ap[tid*52 + q] * Ew[tid*52 + q];
        wsm[tid] = dts[tid] / fmaxf(sqrtf(fmaxf(ss, 0.f)), 1e-12f);
    }
    __syncthreads();
    if (tid == 0) {
        float s = 0.f;
        for (int w = 0; w < NW; w++) s += wsm[w];
        out[v*BT + t] = s / (float)NW;   // improve_sims = sim.T
    }
}

// ------------------------------ launch ----------------------------------
extern "C" void kernel_launch(void* const* d_in, const int* in_sizes, int n_in,
                              void* d_out, int out_size) {
    const float* img   = (const float*)d_in[0];
    const float* cap   = (const float*)d_in[1];
    // d_in[2] = cap_lens (unused by reference math)
    const float* gamma = (const float*)d_in[3];
    const float* beta  = (const float*)d_in[4];
    const float* W1    = (const float*)d_in[5];
    const float* b1    = (const float*)d_in[6];
    const float* W2    = (const float*)d_in[7];
    const float* b2    = (const float*)d_in[8];
    const float* scale = (const float*)d_in[9];
    float* out = (float*)d_out;

    kRowStats<<<BV*LV, 128>>>(img);
    kGloImg<<<BV, 512>>>(img);
    kGloCap<<<BT, 512>>>(cap);
    kCapRow<<<BT*NW, 128>>>(cap);
    kScore<<<dim3(LV, BV), 128>>>(img);
    kSelect<<<dim3(BT, BV), 256>>>(out);
    kExtra<<<BV, 256>>>(img);
    kPrepG1<<<(CC*HH + 255)/256, 256>>>(W1, gamma);
    kPrepCol<<<HH, 128>>>(W1, beta, b1);

    cudaFuncSetAttribute(kHL, cudaFuncAttributeMaxDynamicSharedMemorySize, SMEM_HL);
    kHL<<<dim3(BV, 2), 256, SMEM_HL>>>(img, W2, b2, scale);

    cudaFuncSetAttribute(kE2, cudaFuncAttributeMaxDynamicSharedMemorySize, SMEM_E2);
    kE2<<<dim3(BT, BV), 256, SMEM_E2>>>(img, cap, out);
}

// round 17
// speedup vs baseline: 1.0089x; 1.0025x over previous
#include <cuda_runtime.h>
#include <math.h>

#define CC 512
#define LV 196
#define BV 64
#define BT 32
#define NW 24
#define NK 98
#define KP 49
#define HH 102
#define OFFMASK (BV*BT)

typedef unsigned long long ull;

#define FMA2(d, a, b) asm("fma.rn.f32x2 %0, %1, %2, %0;" : "+l"(d) : "l"(a), "l"(b))
__device__ __forceinline__ ull dup2(float w) {
    ull r;
    asm("mov.b64 %0, {%1, %1};" : "=l"(r) : "r"(__float_as_uint(w)));
    return r;
}

// ---------------- device scratch (no allocation allowed) ----------------
__device__ float d_mu[BV*LV];
__device__ float d_rs[BV*LV];
__device__ float d_invn_img[BV*LV];
__device__ float d_imgglo[BV*CC];
__device__ float d_capglo[BT*CC];
__device__ float d_capinv[BT*NW];
__device__ float d_score[BT*BV*LV];
__device__ int   d_kidx[BT*BV*NK];
__device__ float d_wnon[BT*BV*LV];
__device__ float d_extra[BT*BV*CC];
__device__ float d_G1[CC*HH];
__device__ float d_cs[HH];
__device__ float d_bb[HH];
__device__ float d_L[BV*LV*KP];   // precomputed (scaled) logits per (v,l,p)

// ---------------- row stats for img: mean, rsigma(LN), inv l2 norm ------
__global__ void kRowStats(const float* __restrict__ img) {
    int row = blockIdx.x;  // v*LV + l
    const float* p = img + (size_t)row * CC;
    float s = 0.f, ss = 0.f;
    for (int c = threadIdx.x; c < CC; c += 128) { float x = p[c]; s += x; ss += x * x; }
    __shared__ float r1[128], r2[128];
    r1[threadIdx.x] = s; r2[threadIdx.x] = ss; __syncthreads();
    for (int o = 64; o > 0; o >>= 1) {
        if (threadIdx.x < o) { r1[threadIdx.x] += r1[threadIdx.x+o]; r2[threadIdx.x] += r2[threadIdx.x+o]; }
        __syncthreads();
    }
    if (threadIdx.x == 0) {
        float sum = r1[0], sq = r2[0];
        float mu = sum / CC;
        float var = sq / CC - mu * mu;
        d_mu[row] = mu;
        d_rs[row] = rsqrtf(var + 1e-5f);
        d_invn_img[row] = 1.f / fmaxf(sqrtf(sq), 1e-12f);
    }
}

// ---------------- fused: glo-img, glo-cap, cap row norms, G1 fold -------
// blocks [0,64): kGloImg | [64,96): kGloCap | [96,864): kCapRow | [864,1068): kPrepG1
__global__ void kNorms(const float* __restrict__ img, const float* __restrict__ cap,
                       const float* __restrict__ W1, const float* __restrict__ gamma) {
    int blk = blockIdx.x;
    int c = threadIdx.x;   // 512 threads
    __shared__ float red[512];

    if (blk < BV) {
        int b = blk;
        float acc = 0.f;
        for (int l = 0; l < LV; l++) acc += img[((size_t)b*LV + l)*CC + c];
        acc /= (float)LV;
        red[c] = acc * acc; __syncthreads();
        for (int o = 256; o > 0; o >>= 1) { if (c < o) red[c] += red[c+o]; __syncthreads(); }
        float n = fmaxf(sqrtf(red[0]), 1e-12f);
        d_imgglo[b*CC + c] = acc / n;
    } else if (blk < BV + BT) {
        int b = blk - BV;
        float acc = 0.f;
        for (int l = 0; l < NW; l++) acc += cap[((size_t)b*NW + l)*CC + c];
        acc /= (float)NW;
        red[c] = acc * acc; __syncthreads();
        for (int o = 256; o > 0; o >>= 1) { if (c < o) red[c] += red[c+o]; __syncthreads(); }
        float n = fmaxf(sqrtf(red[0]), 1e-12f);
        d_capglo[b*CC + c] = acc / n;
    } else if (blk < BV + BT + BT*NW) {
        int row = blk - (BV + BT);          // t*NW + w
        float x = cap[(size_t)row*CC + c];
        red[c] = x * x; __syncthreads();
        for (int o = 256; o > 0; o >>= 1) { if (c < o) red[c] += red[c+o]; __syncthreads(); }
        if (c == 0) d_capinv[row] = 1.f / fmaxf(sqrtf(red[0]), 1e-12f);
    } else {
        int idx = (blk - (BV + BT + BT*NW)) * 512 + c;
        if (idx < CC*HH) { int cc = idx / HH; d_G1[idx] = gamma[cc] * W1[idx]; }
    }
}

// ---------------- score[t,v,l] = self_attn + cross_attn -----------------
__global__ void kScore(const float* __restrict__ img) {
    int l = blockIdx.x, v = blockIdx.y;
    __shared__ float row[CC];
    const float* p = img + ((size_t)v*LV + l)*CC;
    for (int c = threadIdx.x; c < CC; c += 128) row[c] = p[c];
    __syncthreads();
    int lane = threadIdx.x & 31, wid = threadIdx.x >> 5;
    float inv = d_invn_img[v*LV + l];
    float sp = 0.f;
    #pragma unroll
    for (int e = 0; e < 16; e++) { int c = lane + 32*e; sp += row[c] * d_imgglo[v*CC + c]; }
    for (int o = 16; o; o >>= 1) sp += __shfl_xor_sync(0xffffffffu, sp, o);
    for (int t = wid; t < BT; t += 4) {
        float cp = 0.f;
        #pragma unroll
        for (int e = 0; e < 16; e++) { int c = lane + 32*e; cp += row[c] * d_capglo[t*CC + c]; }
        for (int o = 16; o; o >>= 1) cp += __shfl_xor_sync(0xffffffffu, cp, o);
        if (lane == 0) d_score[((size_t)t*BV + v)*LV + l] = inv * (sp + cp);
    }
}

// ---------------- exact top-K partition via stable rank -----------------
__global__ void kSelect(float* __restrict__ out) {
    int t = blockIdx.x, v = blockIdx.y;
    int tv = t*BV + v;
    __shared__ float s[LV];
    __shared__ float red[256];
    int tid = threadIdx.x;
    if (tid < LV) s[tid] = d_score[(size_t)tv*LV + tid];
    __syncthreads();
    int cnt = 0; float sl = 0.f; bool keep = false;
    if (tid < LV) {
        sl = s[tid];
        for (int j = 0; j < LV; j++) {
            float sj = s[j];
            cnt += (sj > sl) || (sj == sl && j < tid);
        }
        keep = cnt < NK;
        out[OFFMASK + (size_t)tv*LV + tid] = keep ? 1.f : 0.f;
        if (keep) d_kidx[tv*NK + cnt] = tid;
    }
    // softmax over non-kept scores (order-invariant)
    red[tid] = (tid < LV && !keep) ? sl : -INFINITY;
    __syncthreads();
    for (int o = 128; o > 0; o >>= 1) { if (tid < o) red[tid] = fmaxf(red[tid], red[tid+o]); __syncthreads(); }
    float m = red[0];
    __syncthreads();
    float ev = (tid < LV && !keep) ? expf(sl - m) : 0.f;
    red[tid] = ev;
    __syncthreads();
    for (int o = 128; o > 0; o >>= 1) { if (tid < o) red[tid] += red[tid+o]; __syncthreads(); }
    float Z = red[0];
    if (tid < LV) d_wnon[(size_t)tv*LV + tid] = keep ? 0.f : ev / Z;
}

// ---------------- extra tokens: one block per v, all 32 t at once -------
__global__ void kExtra(const float* __restrict__ img) {
    int v = blockIdx.x;
    __shared__ float wn[BT*LV];
    int tid = threadIdx.x;
    for (int idx = tid; idx < BT*LV; idx += 256)
        wn[idx] = d_wnon[((size_t)(idx/LV)*BV + v)*LV + (idx % LV)];
    __syncthreads();
    #pragma unroll
    for (int half = 0; half < 2; half++) {
        int c = tid + 256*half;
        float acc[BT];
        #pragma unroll
        for (int t = 0; t < BT; t++) acc[t] = 0.f;
        for (int l = 0; l < LV; l++) {
            float x = img[((size_t)v*LV + l)*CC + c];
            #pragma unroll
            for (int t = 0; t < BT; t++) acc[t] += wn[t*LV + l] * x;
        }
        #pragma unroll
        for (int t = 0; t < BT; t++) d_extra[((size_t)t*BV + v)*CC + c] = acc[t];
    }
}

// ---------------- column sums (needs d_G1 from kNorms) ------------------
__global__ void kPrepCol(const float* __restrict__ W1, const float* __restrict__ beta,
                         const float* __restrict__ b1) {
    int h = blockIdx.x;
    float s1 = 0.f, s2 = 0.f;
    for (int c = threadIdx.x; c < CC; c += 128) {
        s1 += d_G1[c*HH + h];
        s2 += beta[c] * W1[c*HH + h];
    }
    __shared__ float r1[128], r2[128];
    r1[threadIdx.x] = s1; r2[threadIdx.x] = s2; __syncthreads();
    for (int o = 64; o > 0; o >>= 1) {
        if (threadIdx.x < o) { r1[threadIdx.x] += r1[threadIdx.x+o]; r2[threadIdx.x] += r2[threadIdx.x+o]; }
        __syncthreads();
    }
    if (threadIdx.x == 0) { d_cs[h] = r1[0]; d_bb[h] = r2[0] + b1[h]; }
}

// ---------------- kHL: per (v, row-half) LN-folded MLP -> logits --------
#define HL_FLOATS (6664 + 6656 + 10192 + 5304 + 102 + 102 + 98 + 98 + 49 + 1)
#define SMEM_HL (HL_FLOATS*4)

__global__ void kHL(const float* __restrict__ img, const float* __restrict__ W2,
                    const float* __restrict__ b2, const float* __restrict__ scale) {
    extern __shared__ float sm[];
    float* As  = sm;               // 98 x 68
    float* Gs  = As + 6664;        // 64 x 104
    float* Hs  = Gs + 6656;        // 98 x 104
    float* W2s = Hs + 10192;       // 102 x 52
    float* css = W2s + 5304;       // 102
    float* bbs = css + 102;        // 102
    float* mus = bbs + 102;        // 98
    float* rss = mus + 98;         // 98
    float* b2s = rss + 98;         // 49
    float* ssc = b2s + 49;         // 1

    int v = blockIdx.x, l0 = blockIdx.y * NK;
    int tid = threadIdx.x; int tx = tid & 15, ty = tid >> 4;

    if (tid < NK) {
        int row = v*LV + l0 + tid;
        mus[tid] = d_mu[row];
        rss[tid] = d_rs[row];
    }
    if (tid < HH) { css[tid] = d_cs[tid]; bbs[tid] = d_bb[tid]; }
    if (tid < KP) b2s[tid] = b2[tid];
    if (tid == 0) ssc[0] = scale[0];
    __syncthreads();

    float acc[7][7];
    #pragma unroll
    for (int i = 0; i < 7; i++)
        #pragma unroll
        for (int j = 0; j < 7; j++) acc[i][j] = 0.f;

    for (int k0 = 0; k0 < CC; k0 += 64) {
        for (int idx = tid; idx < NK*16; idx += 256) {
            int r = idx >> 4, q = (idx & 15) << 2;
            *(float4*)&As[r*68 + q] =
                *(const float4*)&img[((size_t)v*LV + l0 + r)*CC + k0 + q];
        }
        for (int idx = tid; idx < 64*HH; idx += 256) {
            int rr = idx / HH, c = idx % HH;
            Gs[rr*104 + c] = d_G1[(k0 + rr)*HH + c];
        }
        __syncthreads();
        #pragma unroll 4
        for (int kk = 0; kk < 64; kk++) {
            float a[7], b[7];
            #pragma unroll
            for (int i = 0; i < 7; i++) { int r = ty + 16*i; if (r > 97) r = 97; a[i] = As[r*68 + kk]; }
            #pragma unroll
            for (int j = 0; j < 7; j++) { int c = tx + 16*j; if (c > 101) c = 101; b[j] = Gs[kk*104 + c]; }
            #pragma unroll
            for (int i = 0; i < 7; i++)
                #pragma unroll
                for (int j = 0; j < 7; j++) acc[i][j] += a[i] * b[j];
        }
        __syncthreads();
    }

    #pragma unroll
    for (int i = 0; i < 7; i++) {
        int r = ty + 16*i;
        if (r < NK) {
            float mu = mus[r], rsg = rss[r];
            #pragma unroll
            for (int j = 0; j < 7; j++) {
                int c = tx + 16*j;
                if (c < HH) {
                    float x = rsg * (acc[i][j] - mu * css[c]) + bbs[c];
                    Hs[r*104 + c] = 0.5f * x * (1.f + erff(x * 0.70710678118654752f));
                }
            }
        }
    }
    for (int idx = tid; idx < HH*KP; idx += 256) {
        int h = idx / KP, p = idx % KP;
        W2s[h*52 + p] = W2[idx];
    }
    __syncthreads();

    float sc = ssc[0];
    for (int idx = tid; idx < NK*KP; idx += 256) {
        int r = idx / KP, p = idx % KP;
        float a2 = b2s[p];
        for (int h = 0; h < HH; h++) a2 += Hs[r*104 + h] * W2s[h*52 + p];
        d_L[((size_t)v*LV + l0 + r)*KP + p] = sc * a2;
    }
}

// ---------------- E2: phase B FFMA2 + phase C on 250 threads ------------
#define OFF_WWT  0
#define OFF_SCT  5600
#define OFF_AT   12400
#define OFF_CPT  16208
#define OFF_GR   17840
#define OFF_SR   20440
#define OFF_AP   21688
#define OFF_EW   22936
#define OFF_INV  24184
#define OFF_DTS  24236
#define OFF_WSM  24260
#define OFF_KIX  24284
#define SMEM_E2  ((24284 + 98) * 4)

__global__ void __launch_bounds__(256, 2)
kE2(const float* __restrict__ img, const float* __restrict__ cap,
    float* __restrict__ out) {
    extern __shared__ float sm[];
    float* WWt = sm + OFF_WWT;   // [k=0..99][p=0..55] k-major softmax weights
    float* SCt = sm + OFF_SCT;   // [k=0..99][c=0..67] gathered tokens (c-tile)
    float* At  = sm + OFF_AT;    // [p=0..55][c=0..67] aggr tokens (49) + extra (row 49) + zeros
    float* CPt = sm + OFF_CPT;   // [w=0..23][c=0..67] normalized caption words
    float* Gr  = sm + OFF_GR;    // 50 x 52
    float* Sr  = sm + OFF_SR;    // 24 x 52
    float* Ap  = sm + OFF_AP;    // 24 x 52
    float* Ew  = sm + OFF_EW;    // 24 x 52
    float* invn= sm + OFF_INV;   // 52
    float* dts = sm + OFF_DTS;   // 24
    float* wsm = sm + OFF_WSM;   // 24
    int*   kix = (int*)(sm + OFF_KIX);

    int t = blockIdx.x, v = blockIdx.y; int tv = t*BV + v;
    int tid = threadIdx.x;

    // ---- init: kix, zero pads ----
    if (tid < NK) kix[tid] = d_kidx[tv*NK + tid];
    for (int i = tid; i < 2*68; i += 256) SCt[98*68 + i] = 0.f;
    for (int i = tid; i < 6*68; i += 256) At[50*68 + i] = 0.f;
    for (int i = tid; i < 2*56; i += 256) WWt[98*56 + i] = 0.f;
    __syncthreads();

    // ---- gather logits (transposed, k-major) ----
    for (int idx = tid; idx < NK*KP; idx += 256) {
        int k = idx / KP, p = idx % KP;
        WWt[k*56 + p] = d_L[((size_t)v*LV + kix[k])*KP + p];
    }
    for (int idx = tid; idx < NK*7; idx += 256) {   // pad cols 49..55
        int k = idx / 7, p = 49 + idx % 7;
        WWt[k*56 + p] = 0.f;
    }
    __syncthreads();
    // softmax over k per p (column-wise, in place)
    if (tid < KP) {
        float m = -INFINITY;
        for (int k = 0; k < NK; k++) m = fmaxf(m, WWt[k*56 + tid]);
        float Z = 0.f;
        for (int k = 0; k < NK; k++) { float e = expf(WWt[k*56 + tid] - m); WWt[k*56 + tid] = e; Z += e; }
        float iz = 1.f / Z;
        for (int k = 0; k < NK; k++) WWt[k*56 + tid] *= iz;
    }
    __syncthreads();

    // ---- phase-C role assignment (250 threads, single union pattern) ----
    bool doC = tid < 250;
    bool isGram = tid < 175;
    int rA0 = 0, rB0 = 0, strB = 7;
    const float* Bbase = At;
    if (isGram)   { rA0 = tid / 7;       rB0 = tid % 7; strB = 7; Bbase = At;  }
    else if (doC) { int s = tid - 175;   rA0 = s / 3;   rB0 = s % 3; strB = 3; Bbase = CPt; }
    float accC[2][8];
    #pragma unroll
    for (int i = 0; i < 2; i++)
        #pragma unroll
        for (int j = 0; j < 8; j++) accC[i][j] = 0.f;

    int pt = tid >> 4;      // phase B: 0..15, active <13
    int ct = tid & 15;

    for (int c0 = 0; c0 < CC; c0 += 64) {
        // ---- phase A: loads ----
        for (int idx = tid; idx < NK*16; idx += 256) {
            int r = idx >> 4, q = idx & 15;
            *(float4*)&SCt[r*68 + (q<<2)] =
                *(const float4*)&img[((size_t)v*LV + kix[r])*CC + c0 + (q<<2)];
        }
        for (int idx = tid; idx < NW*16; idx += 256) {
            int w = idx >> 4, q = idx & 15;
            float4 x = *(const float4*)&cap[((size_t)t*NW + w)*CC + c0 + (q<<2)];
            float iv = d_capinv[t*NW + w];
            x.x *= iv; x.y *= iv; x.z *= iv; x.w *= iv;
            *(float4*)&CPt[w*68 + (q<<2)] = x;
        }
        if (tid < 16)
            *(float4*)&At[49*68 + (tid<<2)] =
                *(const float4*)&d_extra[(size_t)tv*CC + c0 + (tid<<2)];
        __syncthreads();

        // ---- phase B: aggr (FFMA2 over c-pairs; w scalar dup'd) ----
        if (pt < 13) {
            ull c00=0,c01=0,c10=0,c11=0,c20=0,c21=0,c30=0,c31=0;
            #pragma unroll 4
            for (int k = 0; k < 100; k++) {
                float4 w = *(const float4*)&WWt[k*56 + (pt<<2)];
                ulonglong2 s = *(const ulonglong2*)&SCt[k*68 + (ct<<2)];
                ull w0 = dup2(w.x), w1 = dup2(w.y), w2 = dup2(w.z), w3 = dup2(w.w);
                FMA2(c00, w0, s.x); FMA2(c01, w0, s.y);
                FMA2(c10, w1, s.x); FMA2(c11, w1, s.y);
                FMA2(c20, w2, s.x); FMA2(c21, w2, s.y);
                FMA2(c30, w3, s.x); FMA2(c31, w3, s.y);
            }
            int p = pt << 2;
            if (p     < KP) { *(ull*)&At[(p  )*68 + (ct<<2)] = c00; *(ull*)&At[(p  )*68 + (ct<<2) + 2] = c01; }
            if (p + 1 < KP) { *(ull*)&At[(p+1)*68 + (ct<<2)] = c10; *(ull*)&At[(p+1)*68 + (ct<<2) + 2] = c11; }
            if (p + 2 < KP) { *(ull*)&At[(p+2)*68 + (ct<<2)] = c20; *(ull*)&At[(p+2)*68 + (ct<<2) + 2] = c21; }
            if (p + 3 < KP) { *(ull*)&At[(p+3)*68 + (ct<<2)] = c30; *(ull*)&At[(p+3)*68 + (ct<<2) + 2] = c31; }
        }
        __syncthreads();

        // ---- phase C: Gram / Sr accumulation (single union loop, scalar) ----
        if (doC) {
            #pragma unroll
            for (int c4 = 0; c4 < 16; c4++) {
                float4 a0 = *(const float4*)&At[rA0*68 + (c4<<2)];
                float4 a1 = *(const float4*)&At[(rA0 + 25)*68 + (c4<<2)];
                #pragma unroll
                for (int j = 0; j < 8; j++) {
                    float4 b = *(const float4*)&Bbase[(rB0 + strB*j)*68 + (c4<<2)];
                    accC[0][j] += a0.x*b.x + a0.y*b.y + a0.z*b.z + a0.w*b.w;
                    accC[1][j] += a1.x*b.x + a1.y*b.y + a1.z*b.z + a1.w*b.w;
                }
            }
        }
        __syncthreads();
    }

    // ---- dump Gram / Sr to smem ----
    if (isGram) {
        #pragma unroll
        for (int i = 0; i < 2; i++) {
            int p = rA0 + 25*i;
            #pragma unroll
            for (int j = 0; j < 8; j++) {
                int q = rB0 + 7*j;
                if (q < 50) Gr[p*52 + q] = accC[i][j];
            }
        }
    } else if (doC) {
        #pragma unroll
        for (int i = 0; i < 2; i++) {
            int q = rA0 + 25*i;
            #pragma unroll
            for (int j = 0; j < 8; j++) {
                int w = rB0 + 3*j;
                Sr[w*52 + q] = accC[i][j];
            }
        }
    }
    __syncthreads();

    // ---- finalize: invn from Gram diagonal ----
    if (tid < 50) invn[tid] = 1.f / fmaxf(sqrtf(fmaxf(Gr[tid*52 + tid], 0.f)), 1e-12f);
    __syncthreads();

    // ---- per-word softmax over 50 tokens + dt ----
    if (tid < NW) {
        int w = tid;
        float m = -INFINITY;
        for (int p = 0; p < 50; p++) m = fmaxf(m, invn[p] * Sr[w*52 + p]);
        m *= 4.f;
        float Z = 0.f;
        for (int p = 0; p < 50; p++) {
            float e = expf(4.f * invn[p] * Sr[w*52 + p] - m);
            Ew[w*52 + p] = e; Z += e;
        }
        float iz = 1.f / Z;
        float dt = 0.f;
        for (int p = 0; p < 50; p++) {
            float ap = Ew[w*52 + p] * iz * invn[p];   // attn * invn
            Ap[w*52 + p] = ap;
            dt += ap * Sr[w*52 + p];
        }
        dts[w] = dt;
    }
    __syncthreads();
    // ---- y[w,q] = sum_p Ap[w,p] * Gr[p,q]  (into Ew scratch) ----
    for (int idx = tid; idx < NW*50; idx += 256) {
        int w = idx / 50, q = idx % 50;
        float s = 0.f;
        for (int p = 0; p < 50; p++) s += Ap[w*52 + p] * Gr[p*52 + q];
        Ew[w*52 + q] = s;
    }
    __syncthreads();
    if (tid < NW) {
        float ss = 0.f;
        for (int q = 0; q < 50; q++) ss += Ap[tid*52 + q] * Ew[tid*52 + q];
        wsm[tid] = dts[tid] / fmaxf(sqrtf(fmaxf(ss, 0.f)), 1e-12f);
    }
    __syncthreads();
    if (tid == 0) {
        float s = 0.f;
        for (int w = 0; w < NW; w++) s += wsm[w];
        out[v*BT + t] = s / (float)NW;   // improve_sims = sim.T
    }
}

// ------------------------------ launch ----------------------------------
extern "C" void kernel_launch(void* const* d_in, const int* in_sizes, int n_in,
                              void* d_out, int out_size) {
    const float* img   = (const float*)d_in[0];
    const float* cap   = (const float*)d_in[1];
    // d_in[2] = cap_lens (unused by reference math)
    const float* gamma = (const float*)d_in[3];
    const float* beta  = (const float*)d_in[4];
    const float* W1    = (const float*)d_in[5];
    const float* b1    = (const float*)d_in[6];
    const float* W2    = (const float*)d_in[7];
    const float* b2    = (const float*)d_in[8];
    const float* scale = (const float*)d_in[9];
    float* out = (float*)d_out;

    kRowStats<<<BV*LV, 128>>>(img);
    kNorms<<<BV + BT + BT*NW + (CC*HH + 511)/512, 512>>>(img, cap, W1, gamma);
    kScore<<<dim3(LV, BV), 128>>>(img);
    kSelect<<<dim3(BT, BV), 256>>>(out);
    kExtra<<<BV, 256>>>(img);
    kPrepCol<<<HH, 128>>>(W1, beta, b1);

    cudaFuncSetAttribute(kHL, cudaFuncAttributeMaxDynamicSharedMemorySize, SMEM_HL);
    kHL<<<dim3(BV, 2), 256, SMEM_HL>>>(img, W2, b2, scale);

    cudaFuncSetAttribute(kE2, cudaFuncAttributeMaxDynamicSharedMemorySize, SMEM_E2);
    kE2<<<dim3(BT, BV), 256, SMEM_E2>>>(img, cap, out);
}